// round 13
// baseline (speedup 1.0000x reference)
#include <cuda_runtime.h>
#include <cuda_fp16.h>
#include <cstdint>

#define Bn 2
#define Sn 2048
#define Dn 1024
#define Hn 16
#define HDn 64
#define Mn (Bn*Sn)
#define ATT_SCALE 0.125f   /* 64^-0.5 */

// fp16 tensors
static __device__ __half g_xh[(size_t)Mn*Dn];
static __device__ __half g_wqh[(size_t)Dn*Dn], g_wkh[(size_t)Dn*Dn];
static __device__ __half g_wvh[(size_t)Dn*Dn], g_woh[(size_t)Dn*Dn];
static __device__ __half g_qh[(size_t)Mn*Dn], g_kh[(size_t)Mn*Dn], g_vh[(size_t)Mn*Dn];
static __device__ __half g_aoh[(size_t)Mn*Dn];
static __device__ int g_docrange[32];   // [0..15]=start, [16..31]=end

// ---------------------------------------------------------------------------
// fused fp32 -> fp16 convert: grid.y==0 -> x, grid.y==1 -> one of 4 weights
// ---------------------------------------------------------------------------
__global__ __launch_bounds__(256) void cvt_all(
    const float4* __restrict__ x,
    const float4* __restrict__ w0, const float4* __restrict__ w1,
    const float4* __restrict__ w2, const float4* __restrict__ w3,
    __half2* __restrict__ dx,
    __half2* __restrict__ d0, __half2* __restrict__ d1,
    __half2* __restrict__ d2, __half2* __restrict__ d3,
    int nW4)
{
    const float4* s;
    __half2* d;
    int i;
    if (blockIdx.y == 0) {
        i = blockIdx.x * 256 + threadIdx.x;       // full x range (4*nW4)
        s = x; d = dx;
    } else {
        int w = blockIdx.x >> 10;                  // 1024 blocks per weight
        int lb = blockIdx.x & 1023;
        i = lb * 256 + threadIdx.x;
        s = (w == 0) ? w0 : (w == 1) ? w1 : (w == 2) ? w2 : w3;
        d = (w == 0) ? d0 : (w == 1) ? d1 : (w == 2) ? d2 : d3;
        if (i >= nW4) return;
    }
    float4 v = s[i];
    d[2 * i]     = __float22half2_rn(make_float2(v.x, v.y));
    d[2 * i + 1] = __float22half2_rn(make_float2(v.z, v.w));
}

// ---------------------------------------------------------------------------
// doc ranges via sorted-boundary detection (no atomics, no init)
// ---------------------------------------------------------------------------
__global__ __launch_bounds__(1024) void range_all(const int* __restrict__ doc,
                                                  int* __restrict__ dr)
{
    for (int i = threadIdx.x; i < Sn; i += 1024) {
        int d = doc[i];
        if (i == 0 || doc[i - 1] != d) dr[d] = i;
        if (i == Sn - 1 || doc[i + 1] != d) dr[16 + d] = i;
    }
}

// ---------------------------------------------------------------------------
// helpers
// ---------------------------------------------------------------------------
__device__ __forceinline__ uint32_t s2u(const void* p) {
    return (uint32_t)__cvta_generic_to_shared(p);
}

__device__ __forceinline__ void mmah(float* d, const uint32_t* a,
                                     uint32_t b0, uint32_t b1) {
    asm volatile(
        "mma.sync.aligned.m16n8k16.row.col.f32.f16.f16.f32 "
        "{%0,%1,%2,%3},{%4,%5,%6,%7},{%8,%9},{%0,%1,%2,%3};"
        : "+f"(d[0]), "+f"(d[1]), "+f"(d[2]), "+f"(d[3])
        : "r"(a[0]), "r"(a[1]), "r"(a[2]), "r"(a[3]), "r"(b0), "r"(b1));
}

__device__ __forceinline__ void cp16(uint32_t s, const void* g) {
    asm volatile("cp.async.cg.shared.global [%0], [%1], 16;" :: "r"(s), "l"(g));
}

__device__ __forceinline__ uint32_t packh(float a, float b) {
    __half2 h = __float22half2_rn(make_float2(a, b));
    return *(uint32_t*)&h;
}

#define LDSM_X4(r0,r1,r2,r3, addr) \
    asm volatile("ldmatrix.sync.aligned.m8n8.x4.shared.b16 {%0,%1,%2,%3}, [%4];" \
        : "=r"(r0), "=r"(r1), "=r"(r2), "=r"(r3) : "r"(addr))

#define LDSM_X4_T(r0,r1,r2,r3, addr) \
    asm volatile("ldmatrix.sync.aligned.m8n8.x4.trans.shared.b16 {%0,%1,%2,%3}, [%4];" \
        : "=r"(r0), "=r"(r1), "=r"(r2), "=r"(r3) : "r"(addr))

// ---------------------------------------------------------------------------
// Single-fp16 tensor-core GEMM (unified QKV / O). Block 128x128, KT=64,
// cp.async double-buffered, ldmatrix frags. C = A @ W^T + bias.
// ---------------------------------------------------------------------------
#define KT 64
#define PAD 72                   /* halves per smem row: 64 + 8 pad */
#define STAGE (128 * PAD)        /* halves per array per stage */

__global__ __launch_bounds__(256, 2) void gemm_f16(
    const __half* __restrict__ A,
    const __half* __restrict__ B0, const __half* __restrict__ B1,
    const __half* __restrict__ B2,
    const float* __restrict__ bias0, const float* __restrict__ bias1,
    const float* __restrict__ bias2,
    float* __restrict__ C,
    __half* __restrict__ C0, __half* __restrict__ C1, __half* __restrict__ C2,
    int M, int N, int K)
{
    extern __shared__ char dynsmem[];
    __half* sm = (__half*)dynsmem;
    __half* sA = sm;                 // [2][128][PAD]
    __half* sB = sm + 2 * STAGE;

    const int wsel = blockIdx.x >> 3;
    const __half* B = (wsel == 0) ? B0 : (wsel == 1) ? B1 : B2;
    const float* bias = (wsel == 0) ? bias0 : (wsel == 1) ? bias1 : bias2;
    __half* Co = (wsel == 0) ? C0 : (wsel == 1) ? C1 : C2;

    const int m0 = blockIdx.y * 128, n0 = (blockIdx.x & 7) * 128;
    const int tid = threadIdx.x;
    const int lane = tid & 31, wid = tid >> 5;
    const int g = lane >> 2, t = lane & 3;
    const int mBase = (wid & 3) * 32;
    const int nBase = (wid >> 2) * 64;

    // loader: 2 threads per row, each covers 64B = 4 x 16B chunks
    const int lrow = tid >> 1;
    const int lcol = (tid & 1) * 32;           // halves

    const uint32_t sbase = s2u(sm);
    const uint32_t dA = sbase + (uint32_t)(lrow * PAD + lcol) * 2;
    const uint32_t dB = dA + 2 * STAGE * 2;
    const __half* gA = A + (size_t)(m0 + lrow) * K + lcol;
    const __half* gB = B + (size_t)(n0 + lrow) * K + lcol;

    const int arow = lane & 15;
    const int acol = (lane >> 4) << 3;
    const int brow = (lane & 7) + ((lane >> 4) << 3);
    const int bcol = ((lane >> 3) & 1) << 3;

    float acc[2][8][4];
#pragma unroll
    for (int i = 0; i < 2; i++)
#pragma unroll
        for (int j = 0; j < 8; j++)
#pragma unroll
            for (int l = 0; l < 4; l++) acc[i][j][l] = 0.f;

    const int nTiles = K / KT;   // 16

    auto issue = [&](int kt, int buf) {
        uint32_t so = (uint32_t)(buf * STAGE * 2);
#pragma unroll
        for (int c = 0; c < 4; c++) {
            cp16(dA + so + c * 16, gA + kt + c * 8);
            cp16(dB + so + c * 16, gB + kt + c * 8);
        }
        asm volatile("cp.async.commit_group;");
    };

    issue(0, 0);

    for (int tt = 0; tt < nTiles; tt++) {
        const int buf = tt & 1;
        if (tt + 1 < nTiles) {
            issue((tt + 1) * KT, buf ^ 1);
            asm volatile("cp.async.wait_group 1;");
        } else {
            asm volatile("cp.async.wait_group 0;");
        }
        __syncthreads();

        const uint32_t uA = s2u(sA + buf * STAGE);
        const uint32_t uB = s2u(sB + buf * STAGE);

#pragma unroll
        for (int k16 = 0; k16 < KT; k16 += 16) {
            uint32_t af[2][4];
#pragma unroll
            for (int mt = 0; mt < 2; mt++) {
                uint32_t aoff = (uint32_t)(((mBase + mt * 16 + arow) * PAD + k16 + acol) * 2);
                LDSM_X4(af[mt][0], af[mt][1], af[mt][2], af[mt][3], uA + aoff);
            }
#pragma unroll
            for (int np = 0; np < 2; np++) {
                uint32_t bf[2][4];
#pragma unroll
                for (int q = 0; q < 2; q++) {
                    uint32_t boff = (uint32_t)(((nBase + (np * 2 + q) * 16 + brow) * PAD + k16 + bcol) * 2);
                    LDSM_X4(bf[q][0], bf[q][1], bf[q][2], bf[q][3], uB + boff);
                }
#pragma unroll
                for (int q = 0; q < 2; q++)
#pragma unroll
                    for (int mt = 0; mt < 2; mt++) {
                        mmah(acc[mt][4 * np + 2 * q],     af[mt], bf[q][0], bf[q][1]);
                        mmah(acc[mt][4 * np + 2 * q + 1], af[mt], bf[q][2], bf[q][3]);
                    }
            }
        }
        __syncthreads();
    }

#pragma unroll
    for (int mt = 0; mt < 2; mt++) {
        int r0 = m0 + mBase + mt * 16 + g;
#pragma unroll
        for (int nt = 0; nt < 8; nt++) {
            int c = n0 + nBase + nt * 8 + 2 * t;
            float b0v = bias[c], b1v = bias[c + 1];
            float v00 = acc[mt][nt][0] + b0v, v01 = acc[mt][nt][1] + b1v;
            float v10 = acc[mt][nt][2] + b0v, v11 = acc[mt][nt][3] + b1v;
            if (C) {
                *(float2*)&C[(size_t)r0 * N + c] = make_float2(v00, v01);
                *(float2*)&C[(size_t)(r0 + 8) * N + c] = make_float2(v10, v11);
            } else {
                *(uint32_t*)&Co[(size_t)r0 * N + c] = packh(v00, v01);
                *(uint32_t*)&Co[(size_t)(r0 + 8) * N + c] = packh(v10, v11);
            }
        }
    }
}

// ---------------------------------------------------------------------------
// Single-fp16 tensor-core flash attention, doc-block mask + precomputed
// KV ranges. Double-buffered cp.async KV pipeline. 4 CTAs/SM.
// ---------------------------------------------------------------------------
#define AST 72
#define ASB (2 * 64 * AST * 2)   /* bytes per stage: K, V */

__global__ __launch_bounds__(128, 4) void attn_f16(
    const __half* __restrict__ gq, const __half* __restrict__ gk,
    const __half* __restrict__ gv,
    const int* __restrict__ doc, const int* __restrict__ dr,
    __half* __restrict__ ao)
{
    extern __shared__ char dynsmem[];
    __shared__ int qdoc[64], kdoc[2][64];

    const int q0 = blockIdx.x * 64;
    const int h = blockIdx.y, b = blockIdx.z;
    const int tid = threadIdx.x;
    const int lane = tid & 31, w = tid >> 5;
    const int g = lane >> 2, t = lane & 3;
    const int wrow = w * 16;

    if (tid < 64) qdoc[tid] = doc[q0 + tid];

    // Q fragments directly from global
    const size_t rowbase = (size_t)(b * Sn + q0) * Dn + h * HDn;
    uint32_t qf[4][4];
    {
        const size_t r0 = rowbase + (size_t)(wrow + g) * Dn + 2 * t;
        const size_t r8 = rowbase + (size_t)(wrow + g + 8) * Dn + 2 * t;
#pragma unroll
        for (int ks = 0; ks < 4; ks++) {
            int c = ks * 16;
            qf[ks][0] = *(const uint32_t*)&gq[r0 + c];
            qf[ks][1] = *(const uint32_t*)&gq[r8 + c];
            qf[ks][2] = *(const uint32_t*)&gq[r0 + c + 8];
            qf[ks][3] = *(const uint32_t*)&gq[r8 + c + 8];
        }
    }
    __syncthreads();   // qdoc ready

    const int qd0 = qdoc[wrow + g], qd8 = qdoc[wrow + g + 8];
    const int kv_begin = (__ldg(&dr[qdoc[0]]) / 64) * 64;
    const int kv_end   = __ldg(&dr[16 + qdoc[63]]) + 1;
    const int nT = (kv_end - kv_begin + 63) / 64;

    const uint32_t sb0 = s2u(dynsmem);
    const int brow = (lane & 7) + ((lane >> 4) << 3);
    const int bcol = ((lane >> 3) & 1) << 3;
    const uint32_t lmoff = (uint32_t)(((lane & 15) * AST + ((lane >> 4) << 3)) * 2);

    auto stage = [&](int tt) {
        const int buf = tt & 1;
        const int k0 = kv_begin + tt * 64;
        if (tid < 64) kdoc[buf][tid] = doc[k0 + tid];
        const size_t kb = (size_t)(b * Sn + k0) * Dn + h * HDn;
        const uint32_t sst = sb0 + (uint32_t)buf * ASB;
#pragma unroll
        for (int v = 0; v < 4; v++) {
            int e = tid + v * 128;
            int r = e >> 3, cg = (e & 7) * 8;
            size_t src = kb + (size_t)r * Dn + cg;
            uint32_t dst = sst + (uint32_t)((r * AST + cg) * 2);
            cp16(dst,                    gk + src);
            cp16(dst + 64 * AST * 2,     gv + src);
        }
        asm volatile("cp.async.commit_group;");
    };

    float o[8][4];
#pragma unroll
    for (int i = 0; i < 8; i++)
#pragma unroll
        for (int j = 0; j < 4; j++) o[i][j] = 0.f;
    float m0 = -1e30f, m8 = -1e30f, l0 = 0.f, l8 = 0.f;

    stage(0);

    for (int tt = 0; tt < nT; tt++) {
        const int buf = tt & 1;
        if (tt + 1 < nT) {
            stage(tt + 1);
            asm volatile("cp.async.wait_group 1;" ::: "memory");
        } else {
            asm volatile("cp.async.wait_group 0;" ::: "memory");
        }
        __syncthreads();

        const uint32_t uk = sb0 + (uint32_t)buf * ASB;
        const uint32_t uv = uk + 64 * AST * 2;

        // S = Q K^T
        float s[8][4];
#pragma unroll
        for (int i = 0; i < 8; i++)
#pragma unroll
            for (int j = 0; j < 4; j++) s[i][j] = 0.f;
#pragma unroll
        for (int ks = 0; ks < 4; ks++) {
#pragma unroll
            for (int np = 0; np < 2; np++) {
                uint32_t bf[2][4];
#pragma unroll
                for (int q = 0; q < 2; q++) {
                    uint32_t koff = (uint32_t)((((np * 2 + q) * 16 + brow) * AST + ks * 16 + bcol) * 2);
                    LDSM_X4(bf[q][0], bf[q][1], bf[q][2], bf[q][3], uk + koff);
                }
#pragma unroll
                for (int q = 0; q < 2; q++) {
                    mmah(s[4 * np + 2 * q],     qf[ks], bf[q][0], bf[q][1]);
                    mmah(s[4 * np + 2 * q + 1], qf[ks], bf[q][2], bf[q][3]);
                }
            }
        }

        float mx0 = -1e30f, mx8 = -1e30f;
#pragma unroll
        for (int nt = 0; nt < 8; nt++) {
            int kd0 = kdoc[buf][nt * 8 + 2 * t], kd1 = kdoc[buf][nt * 8 + 2 * t + 1];
            s[nt][0] = (qd0 == kd0) ? s[nt][0] * ATT_SCALE : -1e30f;
            s[nt][1] = (qd0 == kd1) ? s[nt][1] * ATT_SCALE : -1e30f;
            s[nt][2] = (qd8 == kd0) ? s[nt][2] * ATT_SCALE : -1e30f;
            s[nt][3] = (qd8 == kd1) ? s[nt][3] * ATT_SCALE : -1e30f;
            mx0 = fmaxf(mx0, fmaxf(s[nt][0], s[nt][1]));
            mx8 = fmaxf(mx8, fmaxf(s[nt][2], s[nt][3]));
        }
        mx0 = fmaxf(mx0, __shfl_xor_sync(0xffffffffu, mx0, 1));
        mx0 = fmaxf(mx0, __shfl_xor_sync(0xffffffffu, mx0, 2));
        mx8 = fmaxf(mx8, __shfl_xor_sync(0xffffffffu, mx8, 1));
        mx8 = fmaxf(mx8, __shfl_xor_sync(0xffffffffu, mx8, 2));
        const float mn0 = fmaxf(m0, mx0), mn8 = fmaxf(m8, mx8);
        const float f0 = __expf(m0 - mn0), f8 = __expf(m8 - mn8);
        float sum0 = 0.f, sum8 = 0.f;
#pragma unroll
        for (int nt = 0; nt < 8; nt++) {
            s[nt][0] = (s[nt][0] > -1e29f) ? __expf(s[nt][0] - mn0) : 0.f;
            s[nt][1] = (s[nt][1] > -1e29f) ? __expf(s[nt][1] - mn0) : 0.f;
            s[nt][2] = (s[nt][2] > -1e29f) ? __expf(s[nt][2] - mn8) : 0.f;
            s[nt][3] = (s[nt][3] > -1e29f) ? __expf(s[nt][3] - mn8) : 0.f;
            sum0 += s[nt][0] + s[nt][1];
            sum8 += s[nt][2] + s[nt][3];
        }
        sum0 += __shfl_xor_sync(0xffffffffu, sum0, 1);
        sum0 += __shfl_xor_sync(0xffffffffu, sum0, 2);
        sum8 += __shfl_xor_sync(0xffffffffu, sum8, 1);
        sum8 += __shfl_xor_sync(0xffffffffu, sum8, 2);
        l0 = l0 * f0 + sum0;  l8 = l8 * f8 + sum8;
        m0 = mn0;             m8 = mn8;
#pragma unroll
        for (int nt = 0; nt < 8; nt++) {
            o[nt][0] *= f0; o[nt][1] *= f0;
            o[nt][2] *= f8; o[nt][3] *= f8;
        }

        // O += P V
#pragma unroll
        for (int ks = 0; ks < 4; ks++) {
            uint32_t pa[4];
            pa[0] = packh(s[2 * ks][0],     s[2 * ks][1]);
            pa[1] = packh(s[2 * ks][2],     s[2 * ks][3]);
            pa[2] = packh(s[2 * ks + 1][0], s[2 * ks + 1][1]);
            pa[3] = packh(s[2 * ks + 1][2], s[2 * ks + 1][3]);
            uint32_t rowoff = (uint32_t)(ks * 16 * AST * 2) + lmoff;
#pragma unroll
            for (int dp = 0; dp < 2; dp++) {
                uint32_t vf[2][4];
#pragma unroll
                for (int q = 0; q < 2; q++) {
                    uint32_t addr = rowoff + (uint32_t)((dp * 2 + q) * 16 * 2);
                    LDSM_X4_T(vf[q][0], vf[q][1], vf[q][2], vf[q][3], uv + addr);
                }
#pragma unroll
                for (int q = 0; q < 2; q++) {
                    mmah(o[4 * dp + 2 * q],     pa, vf[q][0], vf[q][1]);
                    mmah(o[4 * dp + 2 * q + 1], pa, vf[q][2], vf[q][3]);
                }
            }
        }
        __syncthreads();
    }

    const float inv0 = 1.f / l0, inv8 = 1.f / l8;
    const size_t ob0 = rowbase + (size_t)(wrow + g) * Dn;
    const size_t ob8 = rowbase + (size_t)(wrow + g + 8) * Dn;
#pragma unroll
    for (int nt = 0; nt < 8; nt++) {
        int c = nt * 8 + 2 * t;
        *(uint32_t*)&ao[ob0 + c] = packh(o[nt][0] * inv0, o[nt][1] * inv0);
        *(uint32_t*)&ao[ob8 + c] = packh(o[nt][2] * inv8, o[nt][3] * inv8);
    }
}

// ---------------------------------------------------------------------------
extern "C" void kernel_launch(void* const* d_in, const int* in_sizes, int n_in,
                              void* d_out, int out_size)
{
    (void)in_sizes; (void)n_in; (void)out_size;
    const float* x  = (const float*)d_in[0];
    const float* wq = (const float*)d_in[1];
    const float* bq = (const float*)d_in[2];
    const float* wk = (const float*)d_in[3];
    const float* bk = (const float*)d_in[4];
    const float* wv = (const float*)d_in[5];
    const float* bv = (const float*)d_in[6];
    const float* wo = (const float*)d_in[7];
    const float* bo = (const float*)d_in[8];
    const int*  doc = (const int*)d_in[9];
    float* out = (float*)d_out;

    __half *xh, *wqh, *wkh, *wvh, *woh, *qh, *kh, *vh, *aoh;
    int* dr;
    cudaGetSymbolAddress((void**)&xh, g_xh);
    cudaGetSymbolAddress((void**)&wqh, g_wqh);
    cudaGetSymbolAddress((void**)&wkh, g_wkh);
    cudaGetSymbolAddress((void**)&wvh, g_wvh);
    cudaGetSymbolAddress((void**)&woh, g_woh);
    cudaGetSymbolAddress((void**)&qh, g_qh);
    cudaGetSymbolAddress((void**)&kh, g_kh);
    cudaGetSymbolAddress((void**)&vh, g_vh);
    cudaGetSymbolAddress((void**)&aoh, g_aoh);
    cudaGetSymbolAddress((void**)&dr, g_docrange);

    const int nX4 = Mn * Dn / 4, nW4 = Dn * Dn / 4;  // nX4 == 4*nW4 == 4096*256
    dim3 gc(nX4 / 256, 2);
    cvt_all<<<gc, 256>>>((const float4*)x,
        (const float4*)wq, (const float4*)wk, (const float4*)wv, (const float4*)wo,
        (__half2*)xh, (__half2*)wqh, (__half2*)wkh, (__half2*)wvh, (__half2*)woh,
        nW4);
    range_all<<<1, 1024>>>(doc, dr);

    const int gemm_smem = 4 * STAGE * (int)sizeof(__half);  // 73728
    cudaFuncSetAttribute(gemm_f16, cudaFuncAttributeMaxDynamicSharedMemorySize, gemm_smem);

    // fused QKV (fp16 out)
    dim3 ggq(24, Mn / 128);
    gemm_f16<<<ggq, 256, gemm_smem>>>(xh,
        wqh, wkh, wvh, bq, bk, bv,
        nullptr, qh, kh, vh, Mn, Dn, Dn);

    const int attn_smem = 2 * ASB;   // 36864
    cudaFuncSetAttribute(attn_f16, cudaFuncAttributeMaxDynamicSharedMemorySize, attn_smem);
    dim3 ga(Sn / 64, Hn, Bn);
    attn_f16<<<ga, 128, attn_smem>>>(qh, kh, vh, doc, dr, aoh);

    // O projection (fp32 out)
    dim3 ggo(8, Mn / 128);
    gemm_f16<<<ggo, 256, gemm_smem>>>(aoh,
        woh, woh, woh, bo, bo, bo,
        out, nullptr, nullptr, nullptr, Mn, Dn, Dn);
}

// round 14
// speedup vs baseline: 1.0594x; 1.0594x over previous
#include <cuda_runtime.h>
#include <cuda_fp16.h>
#include <cstdint>

#define Bn 2
#define Sn 2048
#define Dn 1024
#define Hn 16
#define HDn 64
#define Mn (Bn*Sn)
#define ATT_SCALE 0.125f   /* 64^-0.5 */

// fp16 tensors
static __device__ __half g_xh[(size_t)Mn*Dn];
static __device__ __half g_wqh[(size_t)Dn*Dn], g_wkh[(size_t)Dn*Dn];
static __device__ __half g_wvh[(size_t)Dn*Dn], g_woh[(size_t)Dn*Dn];
static __device__ __half g_qh[(size_t)Mn*Dn], g_kh[(size_t)Mn*Dn], g_vh[(size_t)Mn*Dn];
static __device__ __half g_aoh[(size_t)Mn*Dn];
static __device__ int g_docrange[32];   // [0..15]=start, [16..31]=end

// ---------------------------------------------------------------------------
// fused fp32 -> fp16 convert: grid.y==0 -> x, grid.y==1 -> one of 4 weights
// ---------------------------------------------------------------------------
__global__ __launch_bounds__(256) void cvt_all(
    const float4* __restrict__ x,
    const float4* __restrict__ w0, const float4* __restrict__ w1,
    const float4* __restrict__ w2, const float4* __restrict__ w3,
    __half2* __restrict__ dx,
    __half2* __restrict__ d0, __half2* __restrict__ d1,
    __half2* __restrict__ d2, __half2* __restrict__ d3,
    int nW4)
{
    const float4* s;
    __half2* d;
    int i;
    if (blockIdx.y == 0) {
        i = blockIdx.x * 256 + threadIdx.x;       // full x range (4*nW4)
        s = x; d = dx;
    } else {
        int w = blockIdx.x >> 10;                  // 1024 blocks per weight
        int lb = blockIdx.x & 1023;
        i = lb * 256 + threadIdx.x;
        s = (w == 0) ? w0 : (w == 1) ? w1 : (w == 2) ? w2 : w3;
        d = (w == 0) ? d0 : (w == 1) ? d1 : (w == 2) ? d2 : d3;
        if (i >= nW4) return;
    }
    float4 v = s[i];
    d[2 * i]     = __float22half2_rn(make_float2(v.x, v.y));
    d[2 * i + 1] = __float22half2_rn(make_float2(v.z, v.w));
}

// ---------------------------------------------------------------------------
// doc ranges via sorted-boundary detection (no atomics, no init)
// ---------------------------------------------------------------------------
__global__ __launch_bounds__(1024) void range_all(const int* __restrict__ doc,
                                                  int* __restrict__ dr)
{
    for (int i = threadIdx.x; i < Sn; i += 1024) {
        int d = doc[i];
        if (i == 0 || doc[i - 1] != d) dr[d] = i;
        if (i == Sn - 1 || doc[i + 1] != d) dr[16 + d] = i;
    }
}

// ---------------------------------------------------------------------------
// helpers
// ---------------------------------------------------------------------------
__device__ __forceinline__ uint32_t s2u(const void* p) {
    return (uint32_t)__cvta_generic_to_shared(p);
}

__device__ __forceinline__ void mmah(float* d, const uint32_t* a,
                                     uint32_t b0, uint32_t b1) {
    asm volatile(
        "mma.sync.aligned.m16n8k16.row.col.f32.f16.f16.f32 "
        "{%0,%1,%2,%3},{%4,%5,%6,%7},{%8,%9},{%0,%1,%2,%3};"
        : "+f"(d[0]), "+f"(d[1]), "+f"(d[2]), "+f"(d[3])
        : "r"(a[0]), "r"(a[1]), "r"(a[2]), "r"(a[3]), "r"(b0), "r"(b1));
}

__device__ __forceinline__ void cp16(uint32_t s, const void* g) {
    asm volatile("cp.async.cg.shared.global [%0], [%1], 16;" :: "r"(s), "l"(g));
}

__device__ __forceinline__ uint32_t packh(float a, float b) {
    __half2 h = __float22half2_rn(make_float2(a, b));
    return *(uint32_t*)&h;
}

#define LDSM_X4(r0,r1,r2,r3, addr) \
    asm volatile("ldmatrix.sync.aligned.m8n8.x4.shared.b16 {%0,%1,%2,%3}, [%4];" \
        : "=r"(r0), "=r"(r1), "=r"(r2), "=r"(r3) : "r"(addr))

#define LDSM_X4_T(r0,r1,r2,r3, addr) \
    asm volatile("ldmatrix.sync.aligned.m8n8.x4.trans.shared.b16 {%0,%1,%2,%3}, [%4];" \
        : "=r"(r0), "=r"(r1), "=r"(r2), "=r"(r3) : "r"(addr))

// ---------------------------------------------------------------------------
// Single-fp16 tensor-core GEMM (unified QKV / O). Block 128x128, KT=32,
// cp.async double-buffered, ldmatrix frags. C = A @ W^T + bias.
// (exact R12 configuration — measured best)
// ---------------------------------------------------------------------------
#define KT 32
#define PAD 40
#define STAGE (128 * PAD)   /* halves per array per stage */

__global__ __launch_bounds__(256, 2) void gemm_f16(
    const __half* __restrict__ A,
    const __half* __restrict__ B0, const __half* __restrict__ B1,
    const __half* __restrict__ B2,
    const float* __restrict__ bias0, const float* __restrict__ bias1,
    const float* __restrict__ bias2,
    float* __restrict__ C,
    __half* __restrict__ C0, __half* __restrict__ C1, __half* __restrict__ C2,
    int M, int N, int K)
{
    extern __shared__ char dynsmem[];
    __half* sm = (__half*)dynsmem;
    __half* sA = sm;                 // [2][128][PAD]
    __half* sB = sm + 2 * STAGE;

    const int wsel = blockIdx.x >> 3;
    const __half* B = (wsel == 0) ? B0 : (wsel == 1) ? B1 : B2;
    const float* bias = (wsel == 0) ? bias0 : (wsel == 1) ? bias1 : bias2;
    __half* Co = (wsel == 0) ? C0 : (wsel == 1) ? C1 : C2;

    const int m0 = blockIdx.y * 128, n0 = (blockIdx.x & 7) * 128;
    const int tid = threadIdx.x;
    const int lane = tid & 31, wid = tid >> 5;
    const int g = lane >> 2, t = lane & 3;
    const int mBase = (wid & 3) * 32;
    const int nBase = (wid >> 2) * 64;

    const int lrow = tid >> 1;
    const int lcol = (tid & 1) * 16;

    const uint32_t sbase = s2u(sm);
    const uint32_t dA = sbase + (uint32_t)(lrow * PAD + lcol) * 2;
    const uint32_t dB = dA + 2 * STAGE * 2;
    const __half* gA = A + (size_t)(m0 + lrow) * K + lcol;
    const __half* gB = B + (size_t)(n0 + lrow) * K + lcol;

    const int arow = lane & 15;
    const int acol = (lane >> 4) << 3;
    const int brow = (lane & 7) + ((lane >> 4) << 3);
    const int bcol = ((lane >> 3) & 1) << 3;

    float acc[2][8][4];
#pragma unroll
    for (int i = 0; i < 2; i++)
#pragma unroll
        for (int j = 0; j < 8; j++)
#pragma unroll
            for (int l = 0; l < 4; l++) acc[i][j][l] = 0.f;

    const int nTiles = K / KT;

    auto issue = [&](int kt, int buf) {
        uint32_t so = (uint32_t)(buf * STAGE * 2);
#pragma unroll
        for (int c = 0; c < 2; c++) {
            cp16(dA + so + c * 16, gA + kt + c * 8);
            cp16(dB + so + c * 16, gB + kt + c * 8);
        }
        asm volatile("cp.async.commit_group;");
    };

    issue(0, 0);

    for (int tt = 0; tt < nTiles; tt++) {
        const int buf = tt & 1;
        if (tt + 1 < nTiles) {
            issue((tt + 1) * KT, buf ^ 1);
            asm volatile("cp.async.wait_group 1;");
        } else {
            asm volatile("cp.async.wait_group 0;");
        }
        __syncthreads();

        const uint32_t uA = s2u(sA + buf * STAGE);
        const uint32_t uB = s2u(sB + buf * STAGE);

#pragma unroll
        for (int k16 = 0; k16 < KT; k16 += 16) {
            uint32_t af[2][4];
#pragma unroll
            for (int mt = 0; mt < 2; mt++) {
                uint32_t aoff = (uint32_t)(((mBase + mt * 16 + arow) * PAD + k16 + acol) * 2);
                LDSM_X4(af[mt][0], af[mt][1], af[mt][2], af[mt][3], uA + aoff);
            }
#pragma unroll
            for (int np = 0; np < 2; np++) {
                uint32_t bf[2][4];
#pragma unroll
                for (int q = 0; q < 2; q++) {
                    uint32_t boff = (uint32_t)(((nBase + (np * 2 + q) * 16 + brow) * PAD + k16 + bcol) * 2);
                    LDSM_X4(bf[q][0], bf[q][1], bf[q][2], bf[q][3], uB + boff);
                }
#pragma unroll
                for (int q = 0; q < 2; q++)
#pragma unroll
                    for (int mt = 0; mt < 2; mt++) {
                        mmah(acc[mt][4 * np + 2 * q],     af[mt], bf[q][0], bf[q][1]);
                        mmah(acc[mt][4 * np + 2 * q + 1], af[mt], bf[q][2], bf[q][3]);
                    }
            }
        }
        __syncthreads();
    }

#pragma unroll
    for (int mt = 0; mt < 2; mt++) {
        int r0 = m0 + mBase + mt * 16 + g;
#pragma unroll
        for (int nt = 0; nt < 8; nt++) {
            int c = n0 + nBase + nt * 8 + 2 * t;
            float b0v = bias[c], b1v = bias[c + 1];
            float v00 = acc[mt][nt][0] + b0v, v01 = acc[mt][nt][1] + b1v;
            float v10 = acc[mt][nt][2] + b0v, v11 = acc[mt][nt][3] + b1v;
            if (C) {
                *(float2*)&C[(size_t)r0 * N + c] = make_float2(v00, v01);
                *(float2*)&C[(size_t)(r0 + 8) * N + c] = make_float2(v10, v11);
            } else {
                *(uint32_t*)&Co[(size_t)r0 * N + c] = packh(v00, v01);
                *(uint32_t*)&Co[(size_t)(r0 + 8) * N + c] = packh(v10, v11);
            }
        }
    }
}

// ---------------------------------------------------------------------------
// Single-fp16 tensor-core flash attention, doc-block mask + precomputed
// KV ranges. Double-buffered cp.async KV pipeline. 4 CTAs/SM.
// ---------------------------------------------------------------------------
#define AST 72
#define ASB (2 * 64 * AST * 2)   /* bytes per stage: K, V */

__global__ __launch_bounds__(128, 4) void attn_f16(
    const __half* __restrict__ gq, const __half* __restrict__ gk,
    const __half* __restrict__ gv,
    const int* __restrict__ doc, const int* __restrict__ dr,
    __half* __restrict__ ao)
{
    extern __shared__ char dynsmem[];
    __shared__ int qdoc[64], kdoc[2][64];

    const int q0 = blockIdx.x * 64;
    const int h = blockIdx.y, b = blockIdx.z;
    const int tid = threadIdx.x;
    const int lane = tid & 31, w = tid >> 5;
    const int g = lane >> 2, t = lane & 3;
    const int wrow = w * 16;

    if (tid < 64) qdoc[tid] = doc[q0 + tid];

    // Q fragments directly from global
    const size_t rowbase = (size_t)(b * Sn + q0) * Dn + h * HDn;
    uint32_t qf[4][4];
    {
        const size_t r0 = rowbase + (size_t)(wrow + g) * Dn + 2 * t;
        const size_t r8 = rowbase + (size_t)(wrow + g + 8) * Dn + 2 * t;
#pragma unroll
        for (int ks = 0; ks < 4; ks++) {
            int c = ks * 16;
            qf[ks][0] = *(const uint32_t*)&gq[r0 + c];
            qf[ks][1] = *(const uint32_t*)&gq[r8 + c];
            qf[ks][2] = *(const uint32_t*)&gq[r0 + c + 8];
            qf[ks][3] = *(const uint32_t*)&gq[r8 + c + 8];
        }
    }
    __syncthreads();   // qdoc ready

    const int qd0 = qdoc[wrow + g], qd8 = qdoc[wrow + g + 8];
    const int kv_begin = (__ldg(&dr[qdoc[0]]) / 64) * 64;
    const int kv_end   = __ldg(&dr[16 + qdoc[63]]) + 1;
    const int nT = (kv_end - kv_begin + 63) / 64;

    const uint32_t sb0 = s2u(dynsmem);
    const int brow = (lane & 7) + ((lane >> 4) << 3);
    const int bcol = ((lane >> 3) & 1) << 3;
    const uint32_t lmoff = (uint32_t)(((lane & 15) * AST + ((lane >> 4) << 3)) * 2);

    auto stage = [&](int tt) {
        const int buf = tt & 1;
        const int k0 = kv_begin + tt * 64;
        if (tid < 64) kdoc[buf][tid] = doc[k0 + tid];
        const size_t kb = (size_t)(b * Sn + k0) * Dn + h * HDn;
        const uint32_t sst = sb0 + (uint32_t)buf * ASB;
#pragma unroll
        for (int v = 0; v < 4; v++) {
            int e = tid + v * 128;
            int r = e >> 3, cg = (e & 7) * 8;
            size_t src = kb + (size_t)r * Dn + cg;
            uint32_t dst = sst + (uint32_t)((r * AST + cg) * 2);
            cp16(dst,                    gk + src);
            cp16(dst + 64 * AST * 2,     gv + src);
        }
        asm volatile("cp.async.commit_group;");
    };

    float o[8][4];
#pragma unroll
    for (int i = 0; i < 8; i++)
#pragma unroll
        for (int j = 0; j < 4; j++) o[i][j] = 0.f;
    float m0 = -1e30f, m8 = -1e30f, l0 = 0.f, l8 = 0.f;

    stage(0);

    for (int tt = 0; tt < nT; tt++) {
        const int buf = tt & 1;
        if (tt + 1 < nT) {
            stage(tt + 1);
            asm volatile("cp.async.wait_group 1;" ::: "memory");
        } else {
            asm volatile("cp.async.wait_group 0;" ::: "memory");
        }
        __syncthreads();

        const uint32_t uk = sb0 + (uint32_t)buf * ASB;
        const uint32_t uv = uk + 64 * AST * 2;

        // S = Q K^T
        float s[8][4];
#pragma unroll
        for (int i = 0; i < 8; i++)
#pragma unroll
            for (int j = 0; j < 4; j++) s[i][j] = 0.f;
#pragma unroll
        for (int ks = 0; ks < 4; ks++) {
#pragma unroll
            for (int np = 0; np < 2; np++) {
                uint32_t bf[2][4];
#pragma unroll
                for (int q = 0; q < 2; q++) {
                    uint32_t koff = (uint32_t)((((np * 2 + q) * 16 + brow) * AST + ks * 16 + bcol) * 2);
                    LDSM_X4(bf[q][0], bf[q][1], bf[q][2], bf[q][3], uk + koff);
                }
#pragma unroll
                for (int q = 0; q < 2; q++) {
                    mmah(s[4 * np + 2 * q],     qf[ks], bf[q][0], bf[q][1]);
                    mmah(s[4 * np + 2 * q + 1], qf[ks], bf[q][2], bf[q][3]);
                }
            }
        }

        float mx0 = -1e30f, mx8 = -1e30f;
#pragma unroll
        for (int nt = 0; nt < 8; nt++) {
            int kd0 = kdoc[buf][nt * 8 + 2 * t], kd1 = kdoc[buf][nt * 8 + 2 * t + 1];
            s[nt][0] = (qd0 == kd0) ? s[nt][0] * ATT_SCALE : -1e30f;
            s[nt][1] = (qd0 == kd1) ? s[nt][1] * ATT_SCALE : -1e30f;
            s[nt][2] = (qd8 == kd0) ? s[nt][2] * ATT_SCALE : -1e30f;
            s[nt][3] = (qd8 == kd1) ? s[nt][3] * ATT_SCALE : -1e30f;
            mx0 = fmaxf(mx0, fmaxf(s[nt][0], s[nt][1]));
            mx8 = fmaxf(mx8, fmaxf(s[nt][2], s[nt][3]));
        }
        mx0 = fmaxf(mx0, __shfl_xor_sync(0xffffffffu, mx0, 1));
        mx0 = fmaxf(mx0, __shfl_xor_sync(0xffffffffu, mx0, 2));
        mx8 = fmaxf(mx8, __shfl_xor_sync(0xffffffffu, mx8, 1));
        mx8 = fmaxf(mx8, __shfl_xor_sync(0xffffffffu, mx8, 2));
        const float mn0 = fmaxf(m0, mx0), mn8 = fmaxf(m8, mx8);
        const float f0 = __expf(m0 - mn0), f8 = __expf(m8 - mn8);
        float sum0 = 0.f, sum8 = 0.f;
#pragma unroll
        for (int nt = 0; nt < 8; nt++) {
            s[nt][0] = (s[nt][0] > -1e29f) ? __expf(s[nt][0] - mn0) : 0.f;
            s[nt][1] = (s[nt][1] > -1e29f) ? __expf(s[nt][1] - mn0) : 0.f;
            s[nt][2] = (s[nt][2] > -1e29f) ? __expf(s[nt][2] - mn8) : 0.f;
            s[nt][3] = (s[nt][3] > -1e29f) ? __expf(s[nt][3] - mn8) : 0.f;
            sum0 += s[nt][0] + s[nt][1];
            sum8 += s[nt][2] + s[nt][3];
        }
        sum0 += __shfl_xor_sync(0xffffffffu, sum0, 1);
        sum0 += __shfl_xor_sync(0xffffffffu, sum0, 2);
        sum8 += __shfl_xor_sync(0xffffffffu, sum8, 1);
        sum8 += __shfl_xor_sync(0xffffffffu, sum8, 2);
        l0 = l0 * f0 + sum0;  l8 = l8 * f8 + sum8;
        m0 = mn0;             m8 = mn8;
#pragma unroll
        for (int nt = 0; nt < 8; nt++) {
            o[nt][0] *= f0; o[nt][1] *= f0;
            o[nt][2] *= f8; o[nt][3] *= f8;
        }

        // O += P V
#pragma unroll
        for (int ks = 0; ks < 4; ks++) {
            uint32_t pa[4];
            pa[0] = packh(s[2 * ks][0],     s[2 * ks][1]);
            pa[1] = packh(s[2 * ks][2],     s[2 * ks][3]);
            pa[2] = packh(s[2 * ks + 1][0], s[2 * ks + 1][1]);
            pa[3] = packh(s[2 * ks + 1][2], s[2 * ks + 1][3]);
            uint32_t rowoff = (uint32_t)(ks * 16 * AST * 2) + lmoff;
#pragma unroll
            for (int dp = 0; dp < 2; dp++) {
                uint32_t vf[2][4];
#pragma unroll
                for (int q = 0; q < 2; q++) {
                    uint32_t addr = rowoff + (uint32_t)((dp * 2 + q) * 16 * 2);
                    LDSM_X4_T(vf[q][0], vf[q][1], vf[q][2], vf[q][3], uv + addr);
                }
#pragma unroll
                for (int q = 0; q < 2; q++) {
                    mmah(o[4 * dp + 2 * q],     pa, vf[q][0], vf[q][1]);
                    mmah(o[4 * dp + 2 * q + 1], pa, vf[q][2], vf[q][3]);
                }
            }
        }
        __syncthreads();
    }

    const float inv0 = 1.f / l0, inv8 = 1.f / l8;
    const size_t ob0 = rowbase + (size_t)(wrow + g) * Dn;
    const size_t ob8 = rowbase + (size_t)(wrow + g + 8) * Dn;
#pragma unroll
    for (int nt = 0; nt < 8; nt++) {
        int c = nt * 8 + 2 * t;
        *(uint32_t*)&ao[ob0 + c] = packh(o[nt][0] * inv0, o[nt][1] * inv0);
        *(uint32_t*)&ao[ob8 + c] = packh(o[nt][2] * inv8, o[nt][3] * inv8);
    }
}

// ---------------------------------------------------------------------------
extern "C" void kernel_launch(void* const* d_in, const int* in_sizes, int n_in,
                              void* d_out, int out_size)
{
    (void)in_sizes; (void)n_in; (void)out_size;
    const float* x  = (const float*)d_in[0];
    const float* wq = (const float*)d_in[1];
    const float* bq = (const float*)d_in[2];
    const float* wk = (const float*)d_in[3];
    const float* bk = (const float*)d_in[4];
    const float* wv = (const float*)d_in[5];
    const float* bv = (const float*)d_in[6];
    const float* wo = (const float*)d_in[7];
    const float* bo = (const float*)d_in[8];
    const int*  doc = (const int*)d_in[9];
    float* out = (float*)d_out;

    __half *xh, *wqh, *wkh, *wvh, *woh, *qh, *kh, *vh, *aoh;
    int* dr;
    cudaGetSymbolAddress((void**)&xh, g_xh);
    cudaGetSymbolAddress((void**)&wqh, g_wqh);
    cudaGetSymbolAddress((void**)&wkh, g_wkh);
    cudaGetSymbolAddress((void**)&wvh, g_wvh);
    cudaGetSymbolAddress((void**)&woh, g_woh);
    cudaGetSymbolAddress((void**)&qh, g_qh);
    cudaGetSymbolAddress((void**)&kh, g_kh);
    cudaGetSymbolAddress((void**)&vh, g_vh);
    cudaGetSymbolAddress((void**)&aoh, g_aoh);
    cudaGetSymbolAddress((void**)&dr, g_docrange);

    const int nX4 = Mn * Dn / 4, nW4 = Dn * Dn / 4;  // nX4 == 4*nW4
    dim3 gc(nX4 / 256, 2);
    cvt_all<<<gc, 256>>>((const float4*)x,
        (const float4*)wq, (const float4*)wk, (const float4*)wv, (const float4*)wo,
        (__half2*)xh, (__half2*)wqh, (__half2*)wkh, (__half2*)wvh, (__half2*)woh,
        nW4);
    range_all<<<1, 1024>>>(doc, dr);

    const int gemm_smem = 4 * STAGE * (int)sizeof(__half);  // 40960
    cudaFuncSetAttribute(gemm_f16, cudaFuncAttributeMaxDynamicSharedMemorySize, gemm_smem);

    // fused QKV (fp16 out)
    dim3 ggq(24, Mn / 128);
    gemm_f16<<<ggq, 256, gemm_smem>>>(xh,
        wqh, wkh, wvh, bq, bk, bv,
        nullptr, qh, kh, vh, Mn, Dn, Dn);

    const int attn_smem = 2 * ASB;   // 36864
    cudaFuncSetAttribute(attn_f16, cudaFuncAttributeMaxDynamicSharedMemorySize, attn_smem);
    dim3 ga(Sn / 64, Hn, Bn);
    attn_f16<<<ga, 128, attn_smem>>>(qh, kh, vh, doc, dr, aoh);

    // O projection (fp32 out)
    dim3 ggo(8, Mn / 128);
    gemm_f16<<<ggo, 256, gemm_smem>>>(aoh,
        woh, woh, woh, bo, bo, bo,
        out, nullptr, nullptr, nullptr, Mn, Dn, Dn);
}